// round 2
// baseline (speedup 1.0000x reference)
#include <cuda_runtime.h>
#include <math.h>

#define BB 2
#define SS 2048
#define DD 1024
#define HH 16
#define DKK 64

// Scratch (module-load allocation; sanctioned workaround, no runtime allocs)
__device__ float g_Q[BB*SS*DD];
__device__ float g_K[BB*SS*DD];
__device__ float g_V[BB*SS*DD];
__device__ float g_O[BB*SS*DD];

// ---------------------------------------------------------------------------
// GEMM: Y[m,n] = sum_k A[m,k] * W[n,k]   (M=4096, N=1024, K=1024, row-major)
// MODE 0: plain store. MODE 1: RoPE epilogue (interleaved pairs per head).
// Block tile 128x64, BK=16, 256 threads, 8x4 micro-tile per thread.
// ---------------------------------------------------------------------------
template<int MODE>
__global__ __launch_bounds__(256) void gemm_nt(const float* __restrict__ A,
                                               const float* __restrict__ W,
                                               float* __restrict__ Y,
                                               const int* __restrict__ tp) {
    __shared__ float sA[16][132];   // [k][m], padded for banks + float4 align
    __shared__ float sB[16][68];    // [k][n]

    const int bm = blockIdx.y, bn = blockIdx.x;
    const int tid = threadIdx.x;
    const int tr  = tid >> 4;       // 0..15
    const int tc  = tid & 15;       // 0..15
    const int row0 = tr * 8;
    const int col0 = tc * 4;

    float acc[8][4];
    #pragma unroll
    for (int i = 0; i < 8; i++)
        #pragma unroll
        for (int j = 0; j < 4; j++) acc[i][j] = 0.f;

    const float* Ab = A + (size_t)bm * 128 * 1024;
    const float* Wb = W + (size_t)bn * 64  * 1024;

    for (int k0 = 0; k0 < 1024; k0 += 16) {
        // Load A tile 128x16 (512 float4, 2 per thread)
        #pragma unroll
        for (int it = 0; it < 2; it++) {
            int lin = tid + it * 256;
            int r = lin >> 2, c4 = lin & 3;
            float4 v = *reinterpret_cast<const float4*>(Ab + (size_t)r * 1024 + k0 + c4 * 4);
            sA[c4*4+0][r] = v.x; sA[c4*4+1][r] = v.y;
            sA[c4*4+2][r] = v.z; sA[c4*4+3][r] = v.w;
        }
        // Load B tile 64x16 (256 float4, 1 per thread)
        {
            int r = tid >> 2, c4 = tid & 3;
            float4 v = *reinterpret_cast<const float4*>(Wb + (size_t)r * 1024 + k0 + c4 * 4);
            sB[c4*4+0][r] = v.x; sB[c4*4+1][r] = v.y;
            sB[c4*4+2][r] = v.z; sB[c4*4+3][r] = v.w;
        }
        __syncthreads();

        #pragma unroll
        for (int k = 0; k < 16; k++) {
            float a[8], b[4];
            #pragma unroll
            for (int i = 0; i < 8; i++) a[i] = sA[k][row0 + i];
            #pragma unroll
            for (int j = 0; j < 4; j++) b[j] = sB[k][col0 + j];
            #pragma unroll
            for (int i = 0; i < 8; i++)
                #pragma unroll
                for (int j = 0; j < 4; j++) acc[i][j] = fmaf(a[i], b[j], acc[i][j]);
        }
        __syncthreads();
    }

    const int gm0 = bm * 128 + row0;
    const int gn0 = bn * 64 + col0;

    if (MODE == 0) {
        #pragma unroll
        for (int i = 0; i < 8; i++) {
            float4 r = make_float4(acc[i][0], acc[i][1], acc[i][2], acc[i][3]);
            *reinterpret_cast<float4*>(Y + (size_t)(gm0 + i) * 1024 + gn0) = r;
        }
    } else {
        // RoPE: head dim DK=64, interleaved pairs (even e, e+1), inv_freq = theta^(-e/64)
        const int dk0 = gn0 & 63;                       // even, multiple of 4
        const double LN_THETA = 9.210340371976184;      // ln(10000)
        const double f0 = exp(-((double)dk0       / 64.0) * LN_THETA);
        const double f1 = exp(-((double)(dk0 + 2) / 64.0) * LN_THETA);
        const double TWO_PI = 6.283185307179586;
        const double INV_2PI = 0.15915494309189535;
        #pragma unroll
        for (int i = 0; i < 8; i++) {
            const int m = gm0 + i;
            const int s = m & (SS - 1);
            const double pos = (double)tp[s];
            float4 r;
            {
                double ang = pos * f0;
                ang -= TWO_PI * floor(ang * INV_2PI);
                float sn, cs; sincosf((float)ang, &sn, &cs);
                r.x = acc[i][0] * cs - acc[i][1] * sn;
                r.y = acc[i][0] * sn + acc[i][1] * cs;
            }
            {
                double ang = pos * f1;
                ang -= TWO_PI * floor(ang * INV_2PI);
                float sn, cs; sincosf((float)ang, &sn, &cs);
                r.z = acc[i][2] * cs - acc[i][3] * sn;
                r.w = acc[i][2] * sn + acc[i][3] * cs;
            }
            *reinterpret_cast<float4*>(Y + (size_t)m * 1024 + gn0) = r;
        }
    }
}

// ---------------------------------------------------------------------------
// Flash attention (fp32, causal). One CTA: 32 q-rows for one (b,h).
// KV tiles of 64. 128 threads. Online softmax, scores staged in smem.
// ---------------------------------------------------------------------------
#define ATTN_SMEM_FLOATS (192*68 + 64)
#define ATTN_SMEM_BYTES  (ATTN_SMEM_FLOATS * 4)

__global__ __launch_bounds__(128) void attn_kernel(const float* __restrict__ Q,
                                                   const float* __restrict__ K,
                                                   const float* __restrict__ V,
                                                   float* __restrict__ O) {
    extern __shared__ float sm[];
    float (*sQ)[68] = (float(*)[68])(sm);            // 32 x 68
    float (*sK)[68] = (float(*)[68])(sm + 32  * 68); // 64 x 68
    float (*sV)[68] = (float(*)[68])(sm + 96  * 68); // 64 x 68
    float (*sS)[68] = (float(*)[68])(sm + 160 * 68); // 32 x 68
    float* sAlpha = sm + 192 * 68;                   // 32
    float* sL     = sAlpha + 32;                     // 32

    const int b  = blockIdx.y >> 4;
    const int h  = blockIdx.y & 15;
    const int q0 = blockIdx.x * 32;
    const int tid = threadIdx.x;

    const size_t base = (size_t)b * SS * DD + (size_t)h * DKK;

    // Load Q tile pre-scaled by 1/sqrt(64) = 0.125
    for (int i = tid; i < 32 * 64; i += 128) {
        int r = i >> 6, c = i & 63;
        sQ[r][c] = Q[base + (size_t)(q0 + r) * DD + c] * 0.125f;
    }

    const int tr = tid >> 4;       // 0..7  -> 4 q-rows each
    const int tc = tid & 15;       // 0..15 -> 4 cols each
    const int r0 = tr * 4, c0 = tc * 4;

    float o[4][4];
    #pragma unroll
    for (int i = 0; i < 4; i++)
        #pragma unroll
        for (int j = 0; j < 4; j++) o[i][j] = 0.f;

    float m_i = -1e30f, l_i = 0.f;   // valid for tid < 32 (softmax row = tid)
    const int qpos = q0 + tid;

    for (int k0 = 0; k0 <= q0 + 31; k0 += 64) {
        __syncthreads();   // previous tile fully consumed before overwrite
        for (int i = tid; i < 64 * 64; i += 128) {
            int r = i >> 6, c = i & 63;
            sK[r][c] = K[base + (size_t)(k0 + r) * DD + c];
            sV[r][c] = V[base + (size_t)(k0 + r) * DD + c];
        }
        __syncthreads();

        // scores S[32x64] = Qs @ K^T
        float sc[4][4];
        #pragma unroll
        for (int i = 0; i < 4; i++)
            #pragma unroll
            for (int j = 0; j < 4; j++) sc[i][j] = 0.f;
        for (int k = 0; k < 64; k++) {
            float a[4], bb[4];
            #pragma unroll
            for (int i = 0; i < 4; i++) a[i]  = sQ[r0 + i][k];
            #pragma unroll
            for (int j = 0; j < 4; j++) bb[j] = sK[c0 + j][k];
            #pragma unroll
            for (int i = 0; i < 4; i++)
                #pragma unroll
                for (int j = 0; j < 4; j++) sc[i][j] = fmaf(a[i], bb[j], sc[i][j]);
        }
        #pragma unroll
        for (int i = 0; i < 4; i++)
            #pragma unroll
            for (int j = 0; j < 4; j++) sS[r0 + i][c0 + j] = sc[i][j];
        __syncthreads();

        // online softmax: one thread per q-row
        if (tid < 32) {
            int jmax = qpos - k0 + 1;          // causal: allow k <= qpos
            if (jmax > 64) jmax = 64;
            float mx = m_i;
            for (int j = 0; j < jmax; j++) mx = fmaxf(mx, sS[tid][j]);
            float alpha = __expf(m_i - mx);
            float sum = 0.f;
            for (int j = 0; j < 64; j++) {
                float p = (j < jmax) ? __expf(sS[tid][j] - mx) : 0.f;
                sS[tid][j] = p;
                sum += p;
            }
            m_i = mx;
            l_i = l_i * alpha + sum;
            sAlpha[tid] = alpha;
        }
        __syncthreads();

        // O = O*alpha + P @ V
        float al[4];
        #pragma unroll
        for (int i = 0; i < 4; i++) {
            al[i] = sAlpha[r0 + i];
            #pragma unroll
            for (int j = 0; j < 4; j++) o[i][j] *= al[i];
        }
        for (int k = 0; k < 64; k++) {
            float p[4], v[4];
            #pragma unroll
            for (int i = 0; i < 4; i++) p[i] = sS[r0 + i][k];
            #pragma unroll
            for (int j = 0; j < 4; j++) v[j] = sV[k][c0 + j];
            #pragma unroll
            for (int i = 0; i < 4; i++)
                #pragma unroll
                for (int j = 0; j < 4; j++) o[i][j] = fmaf(p[i], v[j], o[i][j]);
        }
    }

    if (tid < 32) sL[tid] = l_i;
    __syncthreads();

    #pragma unroll
    for (int i = 0; i < 4; i++) {
        float inv_l = 1.f / sL[r0 + i];
        #pragma unroll
        for (int j = 0; j < 4; j++)
            O[base + (size_t)(q0 + r0 + i) * DD + c0 + j] = o[i][j] * inv_l;
    }
}

// ---------------------------------------------------------------------------
extern "C" void kernel_launch(void* const* d_in, const int* in_sizes, int n_in,
                              void* d_out, int out_size) {
    const float* x  = (const float*)d_in[0];
    const int*   tp = (const int*)  d_in[1];
    const float* Wq = (const float*)d_in[2];
    const float* Wk = (const float*)d_in[3];
    const float* Wv = (const float*)d_in[4];
    const float* Wo = (const float*)d_in[5];

    float *qp, *kp, *vp, *op;
    cudaGetSymbolAddress((void**)&qp, g_Q);
    cudaGetSymbolAddress((void**)&kp, g_K);
    cudaGetSymbolAddress((void**)&vp, g_V);
    cudaGetSymbolAddress((void**)&op, g_O);

    dim3 ggrid(16, 32);   // N/64, M/128

    gemm_nt<1><<<ggrid, 256>>>(x, Wq, qp, tp);
    gemm_nt<1><<<ggrid, 256>>>(x, Wk, kp, tp);
    gemm_nt<0><<<ggrid, 256>>>(x, Wv, vp, nullptr);

    cudaFuncSetAttribute(attn_kernel, cudaFuncAttributeMaxDynamicSharedMemorySize,
                         ATTN_SMEM_BYTES);
    attn_kernel<<<dim3(64, 32), 128, ATTN_SMEM_BYTES>>>(qp, kp, vp, op);

    gemm_nt<0><<<ggrid, 256>>>(op, Wo, (float*)d_out, nullptr);
}

// round 3
// speedup vs baseline: 1.0121x; 1.0121x over previous
#include <cuda_runtime.h>
#include <math.h>

#define BB 2
#define SS 2048
#define DD 1024
#define HH 16
#define DKK 64

// Scratch (module-load allocation; sanctioned workaround, no runtime allocs)
__device__ float g_Q[BB*SS*DD];
__device__ float g_K[BB*SS*DD];
__device__ float g_V[BB*SS*DD];
__device__ float g_O[BB*SS*DD];

// ---------------------------------------------------------------------------
// GEMM: Y[m,n] = sum_k A[m,k] * W[n,k]   (M=4096, N=1024, K=1024, row-major)
// MODE 0: plain store. MODE 1: RoPE epilogue (interleaved pairs per head).
// Block tile 128x64, BK=16, 256 threads, 8x4 micro-tile per thread.
// ---------------------------------------------------------------------------
template<int MODE>
__global__ __launch_bounds__(256) void gemm_nt(const float* __restrict__ A,
                                               const float* __restrict__ W,
                                               float* __restrict__ Y,
                                               const int* __restrict__ tp) {
    __shared__ float sA[16][132];   // [k][m], padded for banks + float4 align
    __shared__ float sB[16][68];    // [k][n]

    const int bm = blockIdx.y, bn = blockIdx.x;
    const int tid = threadIdx.x;
    const int tr  = tid >> 4;       // 0..15
    const int tc  = tid & 15;       // 0..15
    const int row0 = tr * 8;
    const int col0 = tc * 4;

    float acc[8][4];
    #pragma unroll
    for (int i = 0; i < 8; i++)
        #pragma unroll
        for (int j = 0; j < 4; j++) acc[i][j] = 0.f;

    const float* Ab = A + (size_t)bm * 128 * 1024;
    const float* Wb = W + (size_t)bn * 64  * 1024;

    for (int k0 = 0; k0 < 1024; k0 += 16) {
        // Load A tile 128x16 (512 float4, 2 per thread)
        #pragma unroll
        for (int it = 0; it < 2; it++) {
            int lin = tid + it * 256;
            int r = lin >> 2, c4 = lin & 3;
            float4 v = *reinterpret_cast<const float4*>(Ab + (size_t)r * 1024 + k0 + c4 * 4);
            sA[c4*4+0][r] = v.x; sA[c4*4+1][r] = v.y;
            sA[c4*4+2][r] = v.z; sA[c4*4+3][r] = v.w;
        }
        // Load B tile 64x16 (256 float4, 1 per thread)
        {
            int r = tid >> 2, c4 = tid & 3;
            float4 v = *reinterpret_cast<const float4*>(Wb + (size_t)r * 1024 + k0 + c4 * 4);
            sB[c4*4+0][r] = v.x; sB[c4*4+1][r] = v.y;
            sB[c4*4+2][r] = v.z; sB[c4*4+3][r] = v.w;
        }
        __syncthreads();

        #pragma unroll
        for (int k = 0; k < 16; k++) {
            float a[8], b[4];
            #pragma unroll
            for (int i = 0; i < 8; i++) a[i] = sA[k][row0 + i];
            #pragma unroll
            for (int j = 0; j < 4; j++) b[j] = sB[k][col0 + j];
            #pragma unroll
            for (int i = 0; i < 8; i++)
                #pragma unroll
                for (int j = 0; j < 4; j++) acc[i][j] = fmaf(a[i], b[j], acc[i][j]);
        }
        __syncthreads();
    }

    const int gm0 = bm * 128 + row0;
    const int gn0 = bn * 64 + col0;

    if (MODE == 0) {
        #pragma unroll
        for (int i = 0; i < 8; i++) {
            float4 r = make_float4(acc[i][0], acc[i][1], acc[i][2], acc[i][3]);
            *reinterpret_cast<float4*>(Y + (size_t)(gm0 + i) * 1024 + gn0) = r;
        }
    } else {
        // RoPE: head dim DK=64, interleaved pairs (even e, e+1), inv_freq = theta^(-e/64)
        const int dk0 = gn0 & 63;                       // even, multiple of 4
        const double LN_THETA = 9.210340371976184;      // ln(10000)
        const double f0 = exp(-((double)dk0       / 64.0) * LN_THETA);
        const double f1 = exp(-((double)(dk0 + 2) / 64.0) * LN_THETA);
        const double TWO_PI = 6.283185307179586;
        const double INV_2PI = 0.15915494309189535;
        #pragma unroll
        for (int i = 0; i < 8; i++) {
            const int m = gm0 + i;
            const int s = m & (SS - 1);
            const double pos = (double)tp[s];
            float4 r;
            {
                double ang = pos * f0;
                ang -= TWO_PI * floor(ang * INV_2PI);
                float sn, cs; sincosf((float)ang, &sn, &cs);
                r.x = acc[i][0] * cs - acc[i][1] * sn;
                r.y = acc[i][0] * sn + acc[i][1] * cs;
            }
            {
                double ang = pos * f1;
                ang -= TWO_PI * floor(ang * INV_2PI);
                float sn, cs; sincosf((float)ang, &sn, &cs);
                r.z = acc[i][2] * cs - acc[i][3] * sn;
                r.w = acc[i][2] * sn + acc[i][3] * cs;
            }
            *reinterpret_cast<float4*>(Y + (size_t)m * 1024 + gn0) = r;
        }
    }
}

// ---------------------------------------------------------------------------
// Flash attention (fp32, causal). One CTA: 32 q-rows for one (b,h).
// KV tiles of 64. 128 threads. Online softmax, scores staged in smem.
// ---------------------------------------------------------------------------
#define ATTN_SMEM_FLOATS (192*68 + 64)
#define ATTN_SMEM_BYTES  (ATTN_SMEM_FLOATS * 4)

__global__ __launch_bounds__(128) void attn_kernel(const float* __restrict__ Q,
                                                   const float* __restrict__ K,
                                                   const float* __restrict__ V,
                                                   float* __restrict__ O) {
    extern __shared__ float sm[];
    float (*sQ)[68] = (float(*)[68])(sm);            // 32 x 68
    float (*sK)[68] = (float(*)[68])(sm + 32  * 68); // 64 x 68
    float (*sV)[68] = (float(*)[68])(sm + 96  * 68); // 64 x 68
    float (*sS)[68] = (float(*)[68])(sm + 160 * 68); // 32 x 68
    float* sAlpha = sm + 192 * 68;                   // 32
    float* sL     = sAlpha + 32;                     // 32

    const int b  = blockIdx.y >> 4;
    const int h  = blockIdx.y & 15;
    const int q0 = blockIdx.x * 32;
    const int tid = threadIdx.x;

    const size_t base = (size_t)b * SS * DD + (size_t)h * DKK;

    // Load Q tile pre-scaled by 1/sqrt(64) = 0.125
    for (int i = tid; i < 32 * 64; i += 128) {
        int r = i >> 6, c = i & 63;
        sQ[r][c] = Q[base + (size_t)(q0 + r) * DD + c] * 0.125f;
    }

    const int tr = tid >> 4;       // 0..7  -> 4 q-rows each
    const int tc = tid & 15;       // 0..15 -> 4 cols each
    const int r0 = tr * 4, c0 = tc * 4;

    float o[4][4];
    #pragma unroll
    for (int i = 0; i < 4; i++)
        #pragma unroll
        for (int j = 0; j < 4; j++) o[i][j] = 0.f;

    float m_i = -1e30f, l_i = 0.f;   // valid for tid < 32 (softmax row = tid)
    const int qpos = q0 + tid;

    for (int k0 = 0; k0 <= q0 + 31; k0 += 64) {
        __syncthreads();   // previous tile fully consumed before overwrite
        for (int i = tid; i < 64 * 64; i += 128) {
            int r = i >> 6, c = i & 63;
            sK[r][c] = K[base + (size_t)(k0 + r) * DD + c];
            sV[r][c] = V[base + (size_t)(k0 + r) * DD + c];
        }
        __syncthreads();

        // scores S[32x64] = Qs @ K^T
        float sc[4][4];
        #pragma unroll
        for (int i = 0; i < 4; i++)
            #pragma unroll
            for (int j = 0; j < 4; j++) sc[i][j] = 0.f;
        for (int k = 0; k < 64; k++) {
            float a[4], bb[4];
            #pragma unroll
            for (int i = 0; i < 4; i++) a[i]  = sQ[r0 + i][k];
            #pragma unroll
            for (int j = 0; j < 4; j++) bb[j] = sK[c0 + j][k];
            #pragma unroll
            for (int i = 0; i < 4; i++)
                #pragma unroll
                for (int j = 0; j < 4; j++) sc[i][j] = fmaf(a[i], bb[j], sc[i][j]);
        }
        #pragma unroll
        for (int i = 0; i < 4; i++)
            #pragma unroll
            for (int j = 0; j < 4; j++) sS[r0 + i][c0 + j] = sc[i][j];
        __syncthreads();

        // online softmax: one thread per q-row
        if (tid < 32) {
            int jmax = qpos - k0 + 1;          // causal: allow k <= qpos
            if (jmax > 64) jmax = 64;
            float mx = m_i;
            for (int j = 0; j < jmax; j++) mx = fmaxf(mx, sS[tid][j]);
            float alpha = __expf(m_i - mx);
            float sum = 0.f;
            for (int j = 0; j < 64; j++) {
                float p = (j < jmax) ? __expf(sS[tid][j] - mx) : 0.f;
                sS[tid][j] = p;
                sum += p;
            }
            m_i = mx;
            l_i = l_i * alpha + sum;
            sAlpha[tid] = alpha;
        }
        __syncthreads();

        // O = O*alpha + P @ V
        float al[4];
        #pragma unroll
        for (int i = 0; i < 4; i++) {
            al[i] = sAlpha[r0 + i];
            #pragma unroll
            for (int j = 0; j < 4; j++) o[i][j] *= al[i];
        }
        for (int k = 0; k < 64; k++) {
            float p[4], v[4];
            #pragma unroll
            for (int i = 0; i < 4; i++) p[i] = sS[r0 + i][k];
            #pragma unroll
            for (int j = 0; j < 4; j++) v[j] = sV[k][c0 + j];
            #pragma unroll
            for (int i = 0; i < 4; i++)
                #pragma unroll
                for (int j = 0; j < 4; j++) o[i][j] = fmaf(p[i], v[j], o[i][j]);
        }
    }

    if (tid < 32) sL[tid] = l_i;
    __syncthreads();

    #pragma unroll
    for (int i = 0; i < 4; i++) {
        float inv_l = 1.f / sL[r0 + i];
        #pragma unroll
        for (int j = 0; j < 4; j++)
            O[base + (size_t)(q0 + r0 + i) * DD + c0 + j] = o[i][j] * inv_l;
    }
}

// ---------------------------------------------------------------------------
extern "C" void kernel_launch(void* const* d_in, const int* in_sizes, int n_in,
                              void* d_out, int out_size) {
    const float* x  = (const float*)d_in[0];
    const int*   tp = (const int*)  d_in[1];
    const float* Wq = (const float*)d_in[2];
    const float* Wk = (const float*)d_in[3];
    const float* Wv = (const float*)d_in[4];
    const float* Wo = (const float*)d_in[5];

    float *qp, *kp, *vp, *op;
    cudaGetSymbolAddress((void**)&qp, g_Q);
    cudaGetSymbolAddress((void**)&kp, g_K);
    cudaGetSymbolAddress((void**)&vp, g_V);
    cudaGetSymbolAddress((void**)&op, g_O);

    dim3 ggrid(16, 32);   // N/64, M/128

    gemm_nt<1><<<ggrid, 256>>>(x, Wq, qp, tp);
    gemm_nt<1><<<ggrid, 256>>>(x, Wk, kp, tp);
    gemm_nt<0><<<ggrid, 256>>>(x, Wv, vp, nullptr);

    cudaFuncSetAttribute(attn_kernel, cudaFuncAttributeMaxDynamicSharedMemorySize,
                         ATTN_SMEM_BYTES);
    attn_kernel<<<dim3(64, 32), 128, ATTN_SMEM_BYTES>>>(qp, kp, vp, op);

    gemm_nt<0><<<ggrid, 256>>>(op, Wo, (float*)d_out, nullptr);
}